// round 1
// baseline (speedup 1.0000x reference)
#include <cuda_runtime.h>
#include <cuda_bf16.h>

// CapsuleLinear with k-means routing (dot similarity, no squash), GB300 sm_103a.
//
// Shapes: x[64,1152,8] f32, weight[64,16,8] f32.
// Outputs (concatenated in d_out): out[64,64,16] then probs[64,64,1152].
//
// Algebraic reformulation (never build priors[b,o,n,l]):
//   priors[n,:] = W x[n]   (W is [16,8])
//   logits[n]   = priors[n,:]·out_n          = (W^T out_n)·x[n]
//   out[l]      = sum_n p[n] priors[n,l]     = (W (sum_n p[n] x[n]))[l]
//   init out    = W (mean_n x[n])
// -> only x rows (kept in registers) and the tiny 16x8 W are ever touched.

namespace {
constexpr int BATCH   = 64;
constexpr int N_IN    = 1152;
constexpr int LI      = 8;
constexpr int LO      = 16;
constexpr int O_CAPS  = 64;
constexpr int THREADS = 384;
constexpr int NPT     = 3;            // 1152 = 384 * 3
constexpr int NW      = THREADS / 32; // 12 warps
constexpr float EPSV  = 1e-12f;
}

__global__ __launch_bounds__(THREADS, 2)
void caps_route_kernel(const float* __restrict__ x,
                       const float* __restrict__ wgt,
                       float* __restrict__ out_c,
                       float* __restrict__ out_p)
{
    const int bo   = blockIdx.x;          // b*64 + o
    const int b    = bo >> 6;
    const int o    = bo & 63;
    const int tid  = threadIdx.x;
    const int lane = tid & 31;
    const int warp = tid >> 5;

    __shared__ float ws[LO * LI];     // weight[o], 128 f32
    __shared__ float redA[NW];        // softmax max reduce
    __shared__ float redB[NW];        // softmax sum reduce
    __shared__ float tred[NW][LI];    // t-vector reduce
    __shared__ float vsh[LI];         // v = W^T out_n
    __shared__ float onsh[LO];        // normalized centroid

    if (tid < LO * LI) ws[tid] = wgt[o * LO * LI + tid];

    // Each thread owns rows n = tid + k*384, cached in registers.
    float xr[NPT][LI];
    const float4* xb = reinterpret_cast<const float4*>(x + (size_t)b * N_IN * LI);
    #pragma unroll
    for (int k = 0; k < NPT; k++) {
        const int n = tid + k * THREADS;
        float4 a = xb[2 * n];
        float4 c = xb[2 * n + 1];
        xr[k][0] = a.x; xr[k][1] = a.y; xr[k][2] = a.z; xr[k][3] = a.w;
        xr[k][4] = c.x; xr[k][5] = c.y; xr[k][6] = c.z; xr[k][7] = c.w;
    }

    float o_l = 0.0f;   // warp 0, lanes 0..15: current centroid component

    // Reduce per-thread t[8] across block, then warp0 computes o_l = (W t)[lane].
    auto reduce_t_to_out = [&](float tt[LI]) {
        #pragma unroll
        for (int i = 0; i < LI; i++) {
            float v = tt[i];
            #pragma unroll
            for (int off = 16; off; off >>= 1)
                v += __shfl_xor_sync(0xffffffffu, v, off);
            tt[i] = v;
        }
        if (lane == 0) {
            #pragma unroll
            for (int i = 0; i < LI; i++) tred[warp][i] = tt[i];
        }
        __syncthreads();
        if (warp == 0) {
            float tv = 0.0f;
            if (lane < LI) {
                #pragma unroll
                for (int w2 = 0; w2 < NW; w2++) tv += tred[w2][lane];
            }
            const int ll = lane & 15;
            float acc = 0.0f;
            #pragma unroll
            for (int i = 0; i < LI; i++) {
                float ti = __shfl_sync(0xffffffffu, tv, i);
                acc = fmaf(ws[ll * LI + i], ti, acc);
            }
            o_l = acc;   // valid for lanes 0..15
        }
    };

    // ---- initial centroid: t = mean_n x[n] ----
    {
        float t[LI];
        #pragma unroll
        for (int i = 0; i < LI; i++)
            t[i] = (xr[0][i] + xr[1][i] + xr[2][i]) * (1.0f / (float)N_IN);
        reduce_t_to_out(t);
    }

    // ---- 3 routing iterations ----
    #pragma unroll 1
    for (int it = 0; it < 3; it++) {
        // warp 0: normalize centroid, compute v = W^T out_n into vsh
        if (warp == 0) {
            float sq = (lane < LO) ? o_l * o_l : 0.0f;
            #pragma unroll
            for (int off = 8; off; off >>= 1)
                sq += __shfl_xor_sync(0xffffffffu, sq, off);
            float rn = fmaxf(sqrtf(sq), EPSV);
            float on = o_l / rn;
            if (lane < LO) onsh[lane] = on;
            __syncwarp();
            if (lane < LI) {
                float vv = 0.0f;
                #pragma unroll
                for (int l = 0; l < LO; l++)
                    vv = fmaf(ws[l * LI + lane], onsh[l], vv);
                vsh[lane] = vv;
            }
        }
        __syncthreads();

        float v[LI];
        #pragma unroll
        for (int i = 0; i < LI; i++) v[i] = vsh[i];

        // logits for the 3 owned rows
        float lg[NPT];
        #pragma unroll
        for (int k = 0; k < NPT; k++) {
            float a = 0.0f;
            #pragma unroll
            for (int i = 0; i < LI; i++) a = fmaf(v[i], xr[k][i], a);
            lg[k] = a;
        }

        // block max
        float m = fmaxf(lg[0], fmaxf(lg[1], lg[2]));
        #pragma unroll
        for (int off = 16; off; off >>= 1)
            m = fmaxf(m, __shfl_xor_sync(0xffffffffu, m, off));
        if (lane == 0) redA[warp] = m;
        __syncthreads();
        float gm = redA[0];
        #pragma unroll
        for (int w2 = 1; w2 < NW; w2++) gm = fmaxf(gm, redA[w2]);

        // exp + block sum
        float pk[NPT];
        float s = 0.0f;
        #pragma unroll
        for (int k = 0; k < NPT; k++) { pk[k] = expf(lg[k] - gm); s += pk[k]; }
        #pragma unroll
        for (int off = 16; off; off >>= 1)
            s += __shfl_xor_sync(0xffffffffu, s, off);
        if (lane == 0) redB[warp] = s;
        __syncthreads();
        float gs = 0.0f;
        #pragma unroll
        for (int w2 = 0; w2 < NW; w2++) gs += redB[w2];
        float inv = 1.0f / gs;
        #pragma unroll
        for (int k = 0; k < NPT; k++) pk[k] *= inv;

        // final-iteration probs go straight to GMEM (coalesced, stride-1 per k)
        if (it == 2) {
            float* pp = out_p + (size_t)bo * N_IN;
            #pragma unroll
            for (int k = 0; k < NPT; k++) pp[tid + k * THREADS] = pk[k];
        }

        // t = sum_n p[n] * x[n]  (partial), then reduce -> new centroid
        float t[LI];
        #pragma unroll
        for (int i = 0; i < LI; i++)
            t[i] = fmaf(pk[0], xr[0][i], fmaf(pk[1], xr[1][i], pk[2] * xr[2][i]));
        reduce_t_to_out(t);
    }

    if (warp == 0 && lane < LO)
        out_c[(size_t)bo * LO + lane] = o_l;
}

extern "C" void kernel_launch(void* const* d_in, const int* in_sizes, int n_in,
                              void* d_out, int out_size)
{
    const float* x = (const float*)d_in[0];   // [64,1152,8]
    const float* w = (const float*)d_in[1];   // [64,16,8]
    float* out_c = (float*)d_out;                          // [64,64,16]
    float* out_p = out_c + (size_t)BATCH * O_CAPS * LO;    // [64,64,1152]

    caps_route_kernel<<<BATCH * O_CAPS, THREADS>>>(x, w, out_c, out_p);
}

// round 2
// speedup vs baseline: 2.6376x; 2.6376x over previous
#include <cuda_runtime.h>
#include <cuda_bf16.h>

// CapsuleLinear k-means routing (dot sim, no squash) — GB300 sm_103a, round 2.
//
// Reformulation (priors never materialized):
//   logits[n] = (W^T out_n)·x[n],  out ∝ W t,  t = Σ_n e_n x[n]
//   v = W^T(Wt)/||Wt|| = M t / sqrt(t^T M t),  M = W^T W  (8x8, per-CTA const)
// Softmax is computed max-free and unnormalized except in the last iteration
// (normalization direction is scale-invariant).
//
// 128 threads/CTA, 9 rows/thread in registers. One barrier per iteration
// (double-buffered partial-sum smem). Packed 8-way butterfly: 9 shfls.

namespace {
constexpr int BATCH   = 64;
constexpr int N_IN    = 1152;
constexpr int LI      = 8;
constexpr int LO      = 16;
constexpr int O_CAPS  = 64;
constexpr int THREADS = 128;
constexpr int NPT     = 9;            // 1152 = 128 * 9
constexpr int NW      = THREADS / 32; // 4 warps
constexpr float EPSV  = 1e-12f;
constexpr unsigned FULL = 0xffffffffu;
}

__global__ __launch_bounds__(THREADS, 4)
void caps_route_kernel(const float* __restrict__ x,
                       const float* __restrict__ wgt,
                       float* __restrict__ out_c,
                       float* __restrict__ out_p)
{
    const int bo   = blockIdx.x;          // b*64 + o (o fastest -> L2 reuse of x[b])
    const int b    = bo >> 6;
    const int o    = bo & 63;
    const int tid  = threadIdx.x;
    const int lane = tid & 31;
    const int warp = tid >> 5;

    __shared__ float ws[LO * LI];          // weight[o], 128 f32
    __shared__ float Msh[LI * LI];         // M = W^T W
    __shared__ float tred[2][NW][LI];      // double-buffered t partials
    __shared__ float sred[NW];             // final softmax sum partials

    if (tid < LO * LI) ws[tid] = wgt[o * LO * LI + tid];

    // ---- x rows in registers: n = tid + k*128 ----
    float xr[NPT][LI];
    const float4* xb = reinterpret_cast<const float4*>(x + (size_t)b * N_IN * LI);
    #pragma unroll
    for (int k = 0; k < NPT; k++) {
        const int n = tid + k * THREADS;
        float4 a = xb[2 * n];
        float4 c = xb[2 * n + 1];
        xr[k][0] = a.x; xr[k][1] = a.y; xr[k][2] = a.z; xr[k][3] = a.w;
        xr[k][4] = c.x; xr[k][5] = c.y; xr[k][6] = c.z; xr[k][7] = c.w;
    }

    // Packed butterfly: reduce v[8] across the warp in 9 shfls, store to dst[warp][comp].
    auto bstore = [&](const float v[LI], float dst[NW][LI]) {
        const bool h16 = (lane & 16);
        float a[4];
        #pragma unroll
        for (int j = 0; j < 4; j++) {
            float send = h16 ? v[j] : v[j + 4];
            float keep = h16 ? v[j + 4] : v[j];
            a[j] = keep + __shfl_xor_sync(FULL, send, 16);
        }
        const bool h8 = (lane & 8);
        float s0 = h8 ? a[0] : a[2], k0 = h8 ? a[2] : a[0];
        float b0 = k0 + __shfl_xor_sync(FULL, s0, 8);
        float s1 = h8 ? a[1] : a[3], k1 = h8 ? a[3] : a[1];
        float b1 = k1 + __shfl_xor_sync(FULL, s1, 8);
        const bool h4 = (lane & 4);
        float s2 = h4 ? b0 : b1, k2 = h4 ? b1 : b0;
        float c = k2 + __shfl_xor_sync(FULL, s2, 4);
        c += __shfl_xor_sync(FULL, c, 2);
        c += __shfl_xor_sync(FULL, c, 1);
        if ((lane & 3) == 0) dst[warp][lane >> 2] = c;   // comp = (lane>>2)&7
    };

    // ---- init: t = sum_n x[n] (scale-free; normalize absorbs 1/1152) ----
    {
        float t[LI];
        #pragma unroll
        for (int i = 0; i < LI; i++) {
            float s01 = xr[0][i] + xr[1][i];
            float s23 = xr[2][i] + xr[3][i];
            float s45 = xr[4][i] + xr[5][i];
            float s67 = xr[6][i] + xr[7][i];
            t[i] = ((s01 + s23) + (s45 + s67)) + xr[8][i];
        }
        bstore(t, tred[0]);
    }
    __syncthreads();   // ws + tred[0] visible

    // ---- M = W^T W (threads 0..63, one entry each) ----
    if (tid < LI * LI) {
        const int i = tid >> 3, j = tid & 7;
        float m = 0.0f;
        #pragma unroll
        for (int l = 0; l < LO; l++) m = fmaf(ws[l * LI + i], ws[l * LI + j], m);
        Msh[tid] = m;
    }
    __syncthreads();   // Msh visible

    float e[NPT];      // last-iteration unnormalized probs survive the loop

    #pragma unroll
    for (int it = 0; it < 3; it++) {
        const int rb = it & 1;            // read buf: 0,1,0 ; write buf: 1,0,1

        // -- per-warp epilogue: v_i = (M t)_i / max(sqrt(t·Mt), eps), i = lane&7 --
        const int i8 = lane & 7;
        float tl = tred[rb][0][i8] + tred[rb][1][i8] + tred[rb][2][i8] + tred[rb][3][i8];
        float g = 0.0f;
        #pragma unroll
        for (int j = 0; j < LI; j++) {
            float tj = __shfl_sync(FULL, tl, j);
            g = fmaf(Msh[i8 * LI + j], tj, g);
        }
        float sq = tl * g;
        sq += __shfl_xor_sync(FULL, sq, 4);
        sq += __shfl_xor_sync(FULL, sq, 2);
        sq += __shfl_xor_sync(FULL, sq, 1);
        float rn = fmaxf(sqrtf(sq), EPSV);
        float vi = g * __fdividef(1.0f, rn);

        // -- logits for 9 owned rows (v broadcast by shfl, 9 independent FMA chains) --
        float acc[NPT];
        #pragma unroll
        for (int k = 0; k < NPT; k++) acc[k] = 0.0f;
        #pragma unroll
        for (int j = 0; j < LI; j++) {
            float vj = __shfl_sync(FULL, vi, j);
            #pragma unroll
            for (int k = 0; k < NPT; k++) acc[k] = fmaf(vj, xr[k][j], acc[k]);
        }

        // -- max-free exp (|logit| small: safe in fp32) --
        #pragma unroll
        for (int k = 0; k < NPT; k++) e[k] = __expf(acc[k]);

        // last iteration: reduce softmax sum S too
        if (it == 2) {
            float S = 0.0f;
            #pragma unroll
            for (int k = 0; k < NPT; k++) S += e[k];
            S += __shfl_xor_sync(FULL, S, 16);
            S += __shfl_xor_sync(FULL, S, 8);
            S += __shfl_xor_sync(FULL, S, 4);
            S += __shfl_xor_sync(FULL, S, 2);
            S += __shfl_xor_sync(FULL, S, 1);
            if (lane == 0) sred[warp] = S;
        }

        // -- new t partial: t = Σ_k e_k x_k (unnormalized) --
        float t[LI];
        #pragma unroll
        for (int i = 0; i < LI; i++) {
            float a = e[0] * xr[0][i];
            #pragma unroll
            for (int k = 1; k < NPT; k++) a = fmaf(e[k], xr[k][i], a);
            t[i] = a;
        }
        bstore(t, tred[rb ^ 1]);
        __syncthreads();
    }

    // ---- outputs ----
    const float S = sred[0] + sred[1] + sred[2] + sred[3];
    const float inv = __fdividef(1.0f, S);

    float* pp = out_p + (size_t)bo * N_IN;
    #pragma unroll
    for (int k = 0; k < NPT; k++) pp[tid + k * THREADS] = e[k] * inv;

    if (tid < LO) {   // final centroid: out = W t_final / S  (iter2 wrote buf 1)
        float a = 0.0f;
        #pragma unroll
        for (int j = 0; j < LI; j++) {
            float tj = tred[1][0][j] + tred[1][1][j] + tred[1][2][j] + tred[1][3][j];
            a = fmaf(ws[tid * LI + j], tj, a);
        }
        out_c[(size_t)bo * LO + tid] = a * inv;
    }
}

extern "C" void kernel_launch(void* const* d_in, const int* in_sizes, int n_in,
                              void* d_out, int out_size)
{
    const float* x = (const float*)d_in[0];   // [64,1152,8]
    const float* w = (const float*)d_in[1];   // [64,16,8]
    float* out_c = (float*)d_out;                          // [64,64,16]
    float* out_p = out_c + (size_t)BATCH * O_CAPS * LO;    // [64,64,1152]

    caps_route_kernel<<<BATCH * O_CAPS, THREADS>>>(x, w, out_c, out_p);
}